// round 9
// baseline (speedup 1.0000x reference)
#include <cuda_runtime.h>
#include <cuda_fp16.h>
#include <cstdint>

#define BB 16
#define SS 4096
#define DD 64
#define KPP 256
#define SCALE 0.125f

// ---------------- device scratch ----------------
__device__ __half g_part8h[8 * 2 * 16 * 256 * 64]; // fp16 partials, 8MB
__device__ __half g_WH[2 * 8 * 16 * 8192];         // W A-atoms
__device__ __half g_XH[2 * 16 * 8 * 16 * 2048];    // X B-atoms
__device__ __half g_KpH[BB * 256 * 64];            // Kp B-atoms (n=kp, k=d)
__device__ __half g_VpH[BB * 256 * 64];            // Vp B-atoms (n=d, k=kp)

// ---------------- helpers ----------------
__device__ __forceinline__ uint32_t smem_u32(const void* p) {
    uint32_t a;
    asm("{ .reg .u64 t; cvta.to.shared.u64 t, %1; cvt.u32.u64 %0, t; }" : "=r"(a) : "l"(p));
    return a;
}
__device__ __forceinline__ void ldm_x4(uint32_t* r, uint32_t addr) {
    asm volatile("ldmatrix.sync.aligned.m8n8.x4.shared.b16 {%0,%1,%2,%3}, [%4];"
                 : "=r"(r[0]), "=r"(r[1]), "=r"(r[2]), "=r"(r[3]) : "r"(addr));
}
__device__ __forceinline__ void mma_fp16(float* c, const uint32_t* a, const uint32_t* b) {
    asm volatile(
        "mma.sync.aligned.m16n8k16.row.col.f32.f16.f16.f32 "
        "{%0,%1,%2,%3}, {%4,%5,%6,%7}, {%8,%9}, {%0,%1,%2,%3};"
        : "+f"(c[0]), "+f"(c[1]), "+f"(c[2]), "+f"(c[3])
        : "r"(a[0]), "r"(a[1]), "r"(a[2]), "r"(a[3]), "r"(b[0]), "r"(b[1]));
}
__device__ __forceinline__ uint32_t hpk(__half a, __half b) {
    __half2 t = __halves2half2(a, b);
    return *reinterpret_cast<uint32_t*>(&t);
}
__device__ __forceinline__ uint32_t hpk2(float a, float b) {
    __half2 t = __floats2half2_rn(a, b);
    return *reinterpret_cast<uint32_t*>(&t);
}
__device__ __forceinline__ void cpa16(uint32_t dst, const void* src) {
    asm volatile("cp.async.cg.shared.global [%0], [%1], 16;" :: "r"(dst), "l"(src));
}
#define CP_COMMIT asm volatile("cp.async.commit_group;" ::: "memory")
#define CP_WAIT1 asm volatile("cp.async.wait_group 1;" ::: "memory")
#define CP_WAIT0 asm volatile("cp.async.wait_group 0;" ::: "memory")

// ======================================================================
// Kernel 0: combined prepack. grid (8 chunk, 2 proj, 18), 256 thr.
//   z < 16: X -> B-atoms for batch b=z.  z >= 16: W -> A-atoms, 8 stages.
// ======================================================================
__global__ __launch_bounds__(256) void prepack_all(const float* __restrict__ Kin,
                                                   const float* __restrict__ Vin,
                                                   const float* __restrict__ Ew,
                                                   const float* __restrict__ Fw) {
    const int tid = threadIdx.x;
    const int chunk = blockIdx.x, proj = blockIdx.y, z = blockIdx.z;

    if (z < 16) {
        const int b = z;
        const float* X = (proj ? Vin : Kin) + ((size_t)b * SS + chunk * 512) * DD;
        const size_t xb0 = (size_t)(((proj * 16 + b) * 8 + chunk) * 16) * 2048;
        const int d = tid & 63, sg = tid >> 6;
        const size_t soff = (size_t)(((d >> 3) * 4 + sg) * 64 + (d & 7) * 8);
#pragma unroll 4
        for (int st = 0; st < 16; ++st) {
            const float* col = X + (size_t)(st * 32 + sg * 8) * DD + d;
            float v[8];
#pragma unroll
            for (int e = 0; e < 8; ++e) v[e] = col[e * DD];
            *(uint4*)&g_XH[xb0 + (size_t)st * 2048 + soff] =
                make_uint4(hpk2(v[0], v[1]), hpk2(v[2], v[3]), hpk2(v[4], v[5]), hpk2(v[6], v[7]));
        }
    } else {
        const int stg = z - 16; // 0 or 1 -> stages [stg*8, stg*8+8)
        const int m = tid;
        const float* wrow = (proj ? Fw : Ew) + (size_t)m * SS + chunk * 512;
#pragma unroll
        for (int si = 0; si < 8; ++si) {
            int st = stg * 8 + si;
            const float* src = wrow + st * 32;
            const size_t bb = (size_t)((proj * 8 + chunk) * 16 + st) * 8192;
            float4 f[8];
#pragma unroll
            for (int j = 0; j < 8; ++j) f[j] = *(const float4*)(src + j * 4);
#pragma unroll
            for (int kg = 0; kg < 4; ++kg) {
                float4 a = f[2 * kg], bq = f[2 * kg + 1];
                size_t off = bb + (size_t)(((m >> 3) * 4 + kg) * 64 + (m & 7) * 8);
                *(uint4*)&g_WH[off] = make_uint4(hpk2(a.x, a.y), hpk2(a.z, a.w),
                                                 hpk2(bq.x, bq.y), hpk2(bq.z, bq.w));
            }
        }
    }
}

extern __shared__ __align__(1024) char dsm[];

// ======================================================================
// Kernel 1: projections (validated), epilogue -> fp16 partials.
// ======================================================================
__global__ __launch_bounds__(256, 2) void proj_mma() {
    uint32_t smb = smem_u32(dsm);
    const int tid = threadIdx.x, lane = tid & 31, w = tid >> 5;
    const int chunk = blockIdx.x, proj = blockIdx.y, b = blockIdx.z;
    const int wm = w & 3, wn = w >> 2;
    const int b3 = (lane >> 3) & 1, b4 = lane >> 4, r7 = (lane & 7) * 16;

    const uint4* wp0 = (const uint4*)(g_WH + (size_t)((proj * 8 + chunk) * 16) * 8192);
    const uint4* xp0 = (const uint4*)(g_XH + (size_t)(((proj * 16 + b) * 8 + chunk) * 16) * 2048);

    auto issue = [&](int st) {
        uint32_t base = smb + (uint32_t)(st & 1) * 20480u;
        const uint4* wp = wp0 + (size_t)st * 1024;
        const uint4* xp = xp0 + (size_t)st * 256;
#pragma unroll
        for (int i = 0; i < 4; ++i)
            cpa16(base + (uint32_t)(tid + 256 * i) * 16u, wp + tid + 256 * i);
        cpa16(base + 16384u + (uint32_t)tid * 16u, xp + tid);
    };

    float acc[4][4][4];
#pragma unroll
    for (int i = 0; i < 4; ++i)
#pragma unroll
        for (int j = 0; j < 4; ++j)
#pragma unroll
            for (int e = 0; e < 4; ++e) acc[i][j][e] = 0.f;

    issue(0);
    CP_COMMIT;

    for (int st = 0; st < 16; ++st) {
        if (st < 15) {
            issue(st + 1);
            CP_COMMIT;
            CP_WAIT1;
        } else {
            CP_WAIT0;
        }
        __syncthreads();

        const uint32_t bufb = smb + (uint32_t)(st & 1) * 20480u;
        const uint32_t aH = bufb, bH = bufb + 16384u;

#pragma unroll
        for (int kk2 = 0; kk2 < 2; ++kk2) {
            uint32_t af[4][4], bv[2][4];
#pragma unroll
            for (int mt = 0; mt < 4; ++mt) {
                uint32_t o = (uint32_t)(((wm * 8 + mt * 2 + b3) * 4 + kk2 * 2 + b4) * 128 + r7);
                ldm_x4(af[mt], aH + o);
            }
#pragma unroll
            for (int nt2 = 0; nt2 < 2; ++nt2) {
                uint32_t o = (uint32_t)(((wn * 4 + nt2 * 2 + b4) * 4 + kk2 * 2 + b3) * 128 + r7);
                ldm_x4(bv[nt2], bH + o);
            }
#pragma unroll
            for (int mt = 0; mt < 4; ++mt)
#pragma unroll
                for (int nt2 = 0; nt2 < 2; ++nt2)
#pragma unroll
                    for (int hf = 0; hf < 2; ++hf)
                        mma_fp16(acc[mt][nt2 * 2 + hf], af[mt], &bv[nt2][hf * 2]);
        }
        __syncthreads();
    }

    __half* dst = g_part8h + ((size_t)(chunk * 2 + proj) * 16 + b) * 16384;
    const int row = lane >> 2, q2 = (lane & 3) * 2;
#pragma unroll
    for (int mt = 0; mt < 4; ++mt)
#pragma unroll
        for (int nt = 0; nt < 4; ++nt) {
            int m = wm * 64 + mt * 16 + row;
            int n = wn * 32 + nt * 8 + q2;
            *(uint32_t*)&dst[(size_t)m * 64 + n] = hpk2(acc[mt][nt][0], acc[mt][nt][1]);
            *(uint32_t*)&dst[(size_t)(m + 8) * 64 + n] = hpk2(acc[mt][nt][2], acc[mt][nt][3]);
        }
}

// ======================================================================
// Kernel 2: reduce fp16 partials + bias -> fp16 atoms. grid (16, 2, 16).
// ======================================================================
__global__ __launch_bounds__(256) void proj_reduce_atoms(const float* __restrict__ Eb,
                                                         const float* __restrict__ Fb) {
    __shared__ float tile[32][33];
    const int tid = threadIdx.x;
    const int kpblk = blockIdx.x >> 1, dhalf = blockIdx.x & 1;
    const int p = blockIdx.y, b = blockIdx.z;

    const int r = tid >> 3, c4 = tid & 7;
    float4 acc = make_float4(0.f, 0.f, 0.f, 0.f);
    const size_t eoff = (size_t)(kpblk * 32 + r) * 64 + dhalf * 32 + c4 * 4;
#pragma unroll
    for (int c = 0; c < 8; ++c) {
        uint2 u = *(const uint2*)&g_part8h[((size_t)(c * 2 + p) * 16 + b) * 16384 + eoff];
        float2 v0 = __half22float2(*reinterpret_cast<__half2*>(&u.x));
        float2 v1 = __half22float2(*reinterpret_cast<__half2*>(&u.y));
        acc.x += v0.x; acc.y += v0.y; acc.z += v1.x; acc.w += v1.y;
    }
    const float* bias = p ? Fb : Eb;
    float bv = bias[kpblk * 32 + r];
    tile[r][c4 * 4 + 0] = acc.x + bv;
    tile[r][c4 * 4 + 1] = acc.y + bv;
    tile[r][c4 * 4 + 2] = acc.z + bv;
    tile[r][c4 * 4 + 3] = acc.w + bv;
    __syncthreads();

    if (tid < 128) {
        const int atom = tid >> 3, rr = tid & 7;
        __half h[8];
        if (p == 0) {
            const int g1 = atom >> 2, g2 = atom & 3;
#pragma unroll
            for (int j = 0; j < 8; ++j) h[j] = __float2half(tile[g1 * 8 + rr][g2 * 8 + j]);
            size_t gbase =
                (size_t)b * 16384 + (size_t)(((kpblk * 4 + g1) * 8 + dhalf * 4 + g2)) * 64;
            *(uint4*)&g_KpH[gbase + rr * 8] =
                make_uint4(hpk(h[0], h[1]), hpk(h[2], h[3]), hpk(h[4], h[5]), hpk(h[6], h[7]));
        } else {
            const int gd = atom >> 2, gk = atom & 3;
#pragma unroll
            for (int j = 0; j < 8; ++j) h[j] = __float2half(tile[gk * 8 + j][gd * 8 + rr]);
            size_t gbase =
                (size_t)b * 16384 + (size_t)(((dhalf * 4 + gd) * 32 + kpblk * 4 + gk)) * 64;
            *(uint4*)&g_VpH[gbase + rr * 8] =
                make_uint4(hpk(h[0], h[1]), hpk(h[2], h[3]), hpk(h[4], h[5]), hpk(h[6], h[7]));
        }
    }
}

// ======================================================================
// Kernel 3: fused attention, 2 row-blocks per CTA. grid (32, 16), 2 CTA/SM.
// ======================================================================
#define AT_Q 0
#define AT_KP 8192
#define AT_VP 40960
#define AT_ORED 73728
#define AT_MAX 90624
#define AT_SUM 91136
#define AT_SMEM 91648

__global__ __launch_bounds__(256, 2) void attn_fused(const float* __restrict__ Q,
                                                     float* __restrict__ attnp,
                                                     float* __restrict__ outp) {
    uint32_t smb = smem_u32(dsm);
    const int tid = threadIdx.x, lane = tid & 31, w = tid >> 5;
    const int b = blockIdx.y;

    const int wm = w >> 1, wnh = w & 1;
    const int b3 = (lane >> 3) & 1, b4 = lane >> 4, r7 = (lane & 7) * 16;
    const uint32_t qa = smb + AT_Q;
    const uint32_t kp = smb + AT_KP, vp = smb + AT_VP;
    const int rl = wm * 16 + (lane >> 2);
    float* smax = (float*)(dsm + AT_MAX);
    float* ssum = (float*)(dsm + AT_SUM);
    float* Ored = (float*)(dsm + AT_ORED);
    __half* qsm = (__half*)(dsm + AT_Q);

    // ---- stage Kp/Vp fp16 atoms once (cp.async) ----
    {
        const uint4* kh = (const uint4*)(g_KpH + (size_t)b * 16384);
        const uint4* vh = (const uint4*)(g_VpH + (size_t)b * 16384);
#pragma unroll
        for (int i = 0; i < 8; ++i) {
            uint32_t s = (uint32_t)(tid + 256 * i);
            cpa16(smb + AT_KP + s * 16, kh + s);
            cpa16(smb + AT_VP + s * 16, vh + s);
        }
        CP_COMMIT;
    }

    auto build_q = [&](int s0) {
        const float* Qb = Q + ((size_t)b * SS + s0) * DD;
#pragma unroll
        for (int i = 0; i < 4; ++i) {
            int slot = tid + 256 * i;
            int r = slot >> 4, d4 = slot & 15;
            float4 v = *(const float4*)&Qb[(size_t)r * DD + d4 * 4];
            int off = ((r >> 3) * 8 + (d4 >> 1)) * 64 + (r & 7) * 8 + (d4 & 1) * 4;
            *(uint2*)&qsm[off] =
                make_uint2(hpk2(v.x * SCALE, v.y * SCALE), hpk2(v.z * SCALE, v.w * SCALE));
        }
    };

    build_q(blockIdx.x * 128); // block 0 Q while Kp/Vp fly
    CP_WAIT0;
    __syncthreads();

    for (int blk = 0; blk < 2; ++blk) {
        const int s0 = blockIdx.x * 128 + blk * 64;
        if (blk > 0) {
            __syncthreads();
            build_q(s0);
            __syncthreads();
        }

        // ---- scores: Q @ Kp ----
        float c[16][4];
#pragma unroll
        for (int i = 0; i < 16; ++i)
#pragma unroll
            for (int e = 0; e < 4; ++e) c[i][e] = 0.f;

#pragma unroll
        for (int kk = 0; kk < 4; ++kk) {
            uint32_t aq[4];
            uint32_t oA = (uint32_t)(((wm * 2 + b3) * 8 + kk * 2 + b4) * 128 + r7);
            ldm_x4(aq, qa + oA);
#pragma unroll
            for (int nt2 = 0; nt2 < 8; ++nt2) {
                uint32_t bf[4];
                uint32_t oB = (uint32_t)(((wnh * 16 + nt2 * 2 + b4) * 8 + kk * 2 + b3) * 128 + r7);
                ldm_x4(bf, kp + oB);
                mma_fp16(c[nt2 * 2], aq, &bf[0]);
                mma_fp16(c[nt2 * 2 + 1], aq, &bf[2]);
            }
        }

        // ---- softmax over 256 ----
        float m0 = -1e30f, m1 = -1e30f;
#pragma unroll
        for (int nt = 0; nt < 16; ++nt) {
            m0 = fmaxf(m0, fmaxf(c[nt][0], c[nt][1]));
            m1 = fmaxf(m1, fmaxf(c[nt][2], c[nt][3]));
        }
#pragma unroll
        for (int off = 1; off <= 2; off <<= 1) {
            m0 = fmaxf(m0, __shfl_xor_sync(0xffffffffu, m0, off));
            m1 = fmaxf(m1, __shfl_xor_sync(0xffffffffu, m1, off));
        }
        if ((lane & 3) == 0) {
            smax[wnh * 64 + rl] = m0;
            smax[wnh * 64 + rl + 8] = m1;
        }
        __syncthreads();
        m0 = fmaxf(m0, smax[(wnh ^ 1) * 64 + rl]);
        m1 = fmaxf(m1, smax[(wnh ^ 1) * 64 + rl + 8]);

        float s0a = 0.f, s1a = 0.f;
#pragma unroll
        for (int nt = 0; nt < 16; ++nt) {
            c[nt][0] = __expf(c[nt][0] - m0);
            c[nt][1] = __expf(c[nt][1] - m0);
            c[nt][2] = __expf(c[nt][2] - m1);
            c[nt][3] = __expf(c[nt][3] - m1);
            s0a += c[nt][0] + c[nt][1];
            s1a += c[nt][2] + c[nt][3];
        }
#pragma unroll
        for (int off = 1; off <= 2; off <<= 1) {
            s0a += __shfl_xor_sync(0xffffffffu, s0a, off);
            s1a += __shfl_xor_sync(0xffffffffu, s1a, off);
        }
        if ((lane & 3) == 0) {
            ssum[wnh * 64 + rl] = s0a;
            ssum[wnh * 64 + rl + 8] = s1a;
        }
        __syncthreads();
        float inv0 = 1.f / (s0a + ssum[(wnh ^ 1) * 64 + rl]);
        float inv1 = 1.f / (s1a + ssum[(wnh ^ 1) * 64 + rl + 8]);

        // ---- scale probs + streaming attn write ----
        float* abase = attnp + ((size_t)b * SS + s0 + rl) * KPP + wnh * 128 + (lane & 3) * 2;
#pragma unroll
        for (int nt = 0; nt < 16; ++nt) {
            c[nt][0] *= inv0;
            c[nt][1] *= inv0;
            c[nt][2] *= inv1;
            c[nt][3] *= inv1;
            __stcs((float2*)&abase[nt * 8], make_float2(c[nt][0], c[nt][1]));
            __stcs((float2*)&abase[8 * KPP + nt * 8], make_float2(c[nt][2], c[nt][3]));
        }

        // ---- out GEMM: P @ Vp, k-half per warp ----
        float oc[8][4];
#pragma unroll
        for (int i = 0; i < 8; ++i)
#pragma unroll
            for (int e = 0; e < 4; ++e) oc[i][e] = 0.f;

#pragma unroll
        for (int t2 = 0; t2 < 8; ++t2) {
            uint32_t pa[4];
            pa[0] = hpk2(c[2 * t2][0], c[2 * t2][1]);
            pa[1] = hpk2(c[2 * t2][2], c[2 * t2][3]);
            pa[2] = hpk2(c[2 * t2 + 1][0], c[2 * t2 + 1][1]);
            pa[3] = hpk2(c[2 * t2 + 1][2], c[2 * t2 + 1][3]);
#pragma unroll
            for (int nt2 = 0; nt2 < 4; ++nt2) {
                uint32_t vf[4];
                uint32_t oV =
                    (uint32_t)(((nt2 * 2 + b4) * 32 + wnh * 16 + t2 * 2 + b3) * 128 + r7);
                ldm_x4(vf, vp + oV);
                mma_fp16(oc[nt2 * 2], pa, &vf[0]);
                mma_fp16(oc[nt2 * 2 + 1], pa, &vf[2]);
            }
        }

        // ---- cross-half reduction + out write ----
        if (wnh == 1) {
#pragma unroll
            for (int nt = 0; nt < 8; ++nt) {
                int col = nt * 8 + (lane & 3) * 2;
                *(float2*)&Ored[rl * 66 + col] = make_float2(oc[nt][0], oc[nt][1]);
                *(float2*)&Ored[(rl + 8) * 66 + col] = make_float2(oc[nt][2], oc[nt][3]);
            }
        }
        __syncthreads();
        if (wnh == 0) {
            float* o0 = outp + ((size_t)b * SS + s0 + rl) * DD;
#pragma unroll
            for (int nt = 0; nt < 8; ++nt) {
                int col = nt * 8 + (lane & 3) * 2;
                float2 r0v = *(float2*)&Ored[rl * 66 + col];
                float2 r1v = *(float2*)&Ored[(rl + 8) * 66 + col];
                __stcs((float2*)&o0[col], make_float2(oc[nt][0] + r0v.x, oc[nt][1] + r0v.y));
                __stcs((float2*)&o0[8 * DD + col],
                       make_float2(oc[nt][2] + r1v.x, oc[nt][3] + r1v.y));
            }
        }
    }
}

// ======================================================================
extern "C" void kernel_launch(void* const* d_in, const int* in_sizes, int n_in,
                              void* d_out, int out_size) {
    const float* Q  = (const float*)d_in[0];
    const float* K  = (const float*)d_in[1];
    const float* V  = (const float*)d_in[2];
    const float* Ew = (const float*)d_in[3];
    const float* Eb = (const float*)d_in[4];
    const float* Fw = (const float*)d_in[5];
    const float* Fb = (const float*)d_in[6];

    float* outp  = (float*)d_out;
    float* attnp = outp + (size_t)BB * SS * DD;

    cudaFuncSetAttribute(proj_mma, cudaFuncAttributeMaxDynamicSharedMemorySize, 40960);
    cudaFuncSetAttribute(attn_fused, cudaFuncAttributeMaxDynamicSharedMemorySize, AT_SMEM);

    prepack_all<<<dim3(8, 2, 18), 256>>>(K, V, Ew, Fw);
    proj_mma<<<dim3(8, 2, BB), 256, 40960>>>();
    proj_reduce_atoms<<<dim3(16, 2, BB), 256>>>(Eb, Fb);
    attn_fused<<<dim3(SS / 128, BB), 256, AT_SMEM>>>(Q, attnp, outp);
}

// round 11
// speedup vs baseline: 1.1008x; 1.1008x over previous
#include <cuda_runtime.h>
#include <cuda_fp16.h>
#include <cstdint>

#define BB 16
#define SS 4096
#define DD 64
#define KPP 256
#define SCALE 0.125f

// ---------------- device scratch ----------------
__device__ __half g_part8h[8 * 2 * 16 * 256 * 64]; // fp16 partials, 8MB
__device__ __half g_WH[2 * 8 * 16 * 8192];         // W A-atoms
__device__ __half g_KpH[BB * 256 * 64];            // Kp B-atoms (n=kp, k=d)
__device__ __half g_VpH[BB * 256 * 64];            // Vp B-atoms (n=d, k=kp)

// ---------------- helpers ----------------
__device__ __forceinline__ uint32_t smem_u32(const void* p) {
    uint32_t a;
    asm("{ .reg .u64 t; cvta.to.shared.u64 t, %1; cvt.u32.u64 %0, t; }" : "=r"(a) : "l"(p));
    return a;
}
__device__ __forceinline__ void ldm_x4(uint32_t* r, uint32_t addr) {
    asm volatile("ldmatrix.sync.aligned.m8n8.x4.shared.b16 {%0,%1,%2,%3}, [%4];"
                 : "=r"(r[0]), "=r"(r[1]), "=r"(r[2]), "=r"(r[3]) : "r"(addr));
}
__device__ __forceinline__ void mma_fp16(float* c, const uint32_t* a, const uint32_t* b) {
    asm volatile(
        "mma.sync.aligned.m16n8k16.row.col.f32.f16.f16.f32 "
        "{%0,%1,%2,%3}, {%4,%5,%6,%7}, {%8,%9}, {%0,%1,%2,%3};"
        : "+f"(c[0]), "+f"(c[1]), "+f"(c[2]), "+f"(c[3])
        : "r"(a[0]), "r"(a[1]), "r"(a[2]), "r"(a[3]), "r"(b[0]), "r"(b[1]));
}
__device__ __forceinline__ uint32_t hpk(__half a, __half b) {
    __half2 t = __halves2half2(a, b);
    return *reinterpret_cast<uint32_t*>(&t);
}
__device__ __forceinline__ uint32_t hpk2(float a, float b) {
    __half2 t = __floats2half2_rn(a, b);
    return *reinterpret_cast<uint32_t*>(&t);
}
__device__ __forceinline__ void cpa16(uint32_t dst, const void* src) {
    asm volatile("cp.async.cg.shared.global [%0], [%1], 16;" :: "r"(dst), "l"(src));
}
#define CP_COMMIT asm volatile("cp.async.commit_group;" ::: "memory")
#define CP_WAIT1 asm volatile("cp.async.wait_group 1;" ::: "memory")
#define CP_WAIT0 asm volatile("cp.async.wait_group 0;" ::: "memory")

// ======================================================================
// Kernel 0: prepack W -> fp16 A-atoms. grid (16 st, 8 chunk, 2 proj), 256 thr.
// ======================================================================
__global__ __launch_bounds__(256) void prepack_W(const float* __restrict__ Ew,
                                                 const float* __restrict__ Fw) {
    const int st = blockIdx.x, chunk = blockIdx.y, proj = blockIdx.z;
    const int m = threadIdx.x;
    const float* src = (proj ? Fw : Ew) + (size_t)m * SS + chunk * 512 + st * 32;
    const size_t bb = (size_t)((proj * 8 + chunk) * 16 + st) * 8192;

    float4 f[8];
#pragma unroll
    for (int j = 0; j < 8; ++j) f[j] = *(const float4*)(src + j * 4);
#pragma unroll
    for (int kg = 0; kg < 4; ++kg) {
        float4 a = f[2 * kg], b = f[2 * kg + 1];
        size_t off = bb + (size_t)(((m >> 3) * 4 + kg) * 64 + (m & 7) * 8);
        *(uint4*)&g_WH[off] =
            make_uint4(hpk2(a.x, a.y), hpk2(a.z, a.w), hpk2(b.x, b.y), hpk2(b.z, b.w));
    }
}

extern __shared__ __align__(1024) char dsm[];

// ======================================================================
// Kernel 1: projections. W via cp.async (prepacked), X fused in-kernel:
// LDG fp32 one stage ahead -> convert -> STS fp16 atoms into B slot.
// grid (8 chunk, 2 proj, 16 b), 256 thr, 40KB dyn smem, 2 CTA/SM.
// Per buf (20480 B): A 0..16384, B 16384..20480.
// ======================================================================
__global__ __launch_bounds__(256, 2) void proj_mma(const float* __restrict__ Kin,
                                                   const float* __restrict__ Vin) {
    uint32_t smb = smem_u32(dsm);
    const int tid = threadIdx.x, lane = tid & 31, w = tid >> 5;
    const int chunk = blockIdx.x, proj = blockIdx.y, b = blockIdx.z;
    const int wm = w & 3, wn = w >> 2;
    const int b3 = (lane >> 3) & 1, b4 = lane >> 4, r7 = (lane & 7) * 16;

    const uint4* wp0 = (const uint4*)(g_WH + (size_t)((proj * 8 + chunk) * 16) * 8192);
    const float* X = (proj ? Vin : Kin) + ((size_t)b * SS + chunk * 512) * DD;

    const int xd = tid & 63, xsg = tid >> 6;
    const uint32_t xsts = (uint32_t)((((xd >> 3) * 4 + xsg) * 64 + (xd & 7) * 8) * 2);

    auto issueW = [&](int st) {
        uint32_t base = smb + (uint32_t)(st & 1) * 20480u;
        const uint4* wp = wp0 + (size_t)st * 1024;
#pragma unroll
        for (int i = 0; i < 4; ++i)
            cpa16(base + (uint32_t)(tid + 256 * i) * 16u, wp + tid + 256 * i);
    };
    auto ldgX = [&](int st, float* v) {
        const float* col = X + (size_t)(st * 32 + xsg * 8) * DD + xd;
#pragma unroll
        for (int e = 0; e < 8; ++e) v[e] = col[e * DD];
    };
    auto stsX = [&](int st, const float* v) {
        uint32_t dst = smb + (uint32_t)(st & 1) * 20480u + 16384u + xsts;
        asm volatile("st.shared.v4.b32 [%0], {%1,%2,%3,%4};"
                     :: "r"(dst), "r"(hpk2(v[0], v[1])), "r"(hpk2(v[2], v[3])),
                        "r"(hpk2(v[4], v[5])), "r"(hpk2(v[6], v[7])));
    };

    float acc[4][4][4];
#pragma unroll
    for (int i = 0; i < 4; ++i)
#pragma unroll
        for (int j = 0; j < 4; ++j)
#pragma unroll
            for (int e = 0; e < 4; ++e) acc[i][j][e] = 0.f;

    float xv[8];
    ldgX(0, xv);
    issueW(0);
    CP_COMMIT;
    stsX(0, xv);

    for (int st = 0; st < 16; ++st) {
        if (st < 15) {
            issueW(st + 1);
            CP_COMMIT;
            ldgX(st + 1, xv);
            CP_WAIT1;
        } else {
            CP_WAIT0;
        }
        __syncthreads(); // buf[st]: W cp done (all threads), X STS from prev iter visible

        const uint32_t bufb = smb + (uint32_t)(st & 1) * 20480u;
        const uint32_t aH = bufb, bH = bufb + 16384u;

#pragma unroll
        for (int kk2 = 0; kk2 < 2; ++kk2) {
            uint32_t af[4][4], bv[2][4];
#pragma unroll
            for (int mt = 0; mt < 4; ++mt) {
                uint32_t o = (uint32_t)(((wm * 8 + mt * 2 + b3) * 4 + kk2 * 2 + b4) * 128 + r7);
                ldm_x4(af[mt], aH + o);
            }
#pragma unroll
            for (int nt2 = 0; nt2 < 2; ++nt2) {
                uint32_t o = (uint32_t)(((wn * 4 + nt2 * 2 + b4) * 4 + kk2 * 2 + b3) * 128 + r7);
                ldm_x4(bv[nt2], bH + o);
            }
#pragma unroll
            for (int mt = 0; mt < 4; ++mt)
#pragma unroll
                for (int nt2 = 0; nt2 < 2; ++nt2)
#pragma unroll
                    for (int hf = 0; hf < 2; ++hf)
                        mma_fp16(acc[mt][nt2 * 2 + hf], af[mt], &bv[nt2][hf * 2]);
        }
        if (st < 15) stsX(st + 1, xv); // writes buf[(st+1)&1] — disjoint from buf[st]
        __syncthreads();
    }

    __half* dst = g_part8h + ((size_t)(chunk * 2 + proj) * 16 + b) * 16384;
    const int row = lane >> 2, q2 = (lane & 3) * 2;
#pragma unroll
    for (int mt = 0; mt < 4; ++mt)
#pragma unroll
        for (int nt = 0; nt < 4; ++nt) {
            int m = wm * 64 + mt * 16 + row;
            int n = wn * 32 + nt * 8 + q2;
            *(uint32_t*)&dst[(size_t)m * 64 + n] = hpk2(acc[mt][nt][0], acc[mt][nt][1]);
            *(uint32_t*)&dst[(size_t)(m + 8) * 64 + n] = hpk2(acc[mt][nt][2], acc[mt][nt][3]);
        }
}

// ======================================================================
// Kernel 2: reduce fp16 partials + bias -> fp16 atoms. grid (16, 2, 16).
// ======================================================================
__global__ __launch_bounds__(256) void proj_reduce_atoms(const float* __restrict__ Eb,
                                                         const float* __restrict__ Fb) {
    __shared__ float tile[32][33];
    const int tid = threadIdx.x;
    const int kpblk = blockIdx.x >> 1, dhalf = blockIdx.x & 1;
    const int p = blockIdx.y, b = blockIdx.z;

    const int r = tid >> 3, c4 = tid & 7;
    float4 acc = make_float4(0.f, 0.f, 0.f, 0.f);
    const size_t eoff = (size_t)(kpblk * 32 + r) * 64 + dhalf * 32 + c4 * 4;
#pragma unroll
    for (int c = 0; c < 8; ++c) {
        uint2 u = *(const uint2*)&g_part8h[((size_t)(c * 2 + p) * 16 + b) * 16384 + eoff];
        float2 v0 = __half22float2(*reinterpret_cast<__half2*>(&u.x));
        float2 v1 = __half22float2(*reinterpret_cast<__half2*>(&u.y));
        acc.x += v0.x; acc.y += v0.y; acc.z += v1.x; acc.w += v1.y;
    }
    const float* bias = p ? Fb : Eb;
    float bv = bias[kpblk * 32 + r];
    tile[r][c4 * 4 + 0] = acc.x + bv;
    tile[r][c4 * 4 + 1] = acc.y + bv;
    tile[r][c4 * 4 + 2] = acc.z + bv;
    tile[r][c4 * 4 + 3] = acc.w + bv;
    __syncthreads();

    if (tid < 128) {
        const int atom = tid >> 3, rr = tid & 7;
        __half h[8];
        if (p == 0) {
            const int g1 = atom >> 2, g2 = atom & 3;
#pragma unroll
            for (int j = 0; j < 8; ++j) h[j] = __float2half(tile[g1 * 8 + rr][g2 * 8 + j]);
            size_t gbase =
                (size_t)b * 16384 + (size_t)(((kpblk * 4 + g1) * 8 + dhalf * 4 + g2)) * 64;
            *(uint4*)&g_KpH[gbase + rr * 8] =
                make_uint4(hpk(h[0], h[1]), hpk(h[2], h[3]), hpk(h[4], h[5]), hpk(h[6], h[7]));
        } else {
            const int gd = atom >> 2, gk = atom & 3;
#pragma unroll
            for (int j = 0; j < 8; ++j) h[j] = __float2half(tile[gk * 8 + j][gd * 8 + rr]);
            size_t gbase =
                (size_t)b * 16384 + (size_t)(((dhalf * 4 + gd) * 32 + kpblk * 4 + gk)) * 64;
            *(uint4*)&g_VpH[gbase + rr * 8] =
                make_uint4(hpk(h[0], h[1]), hpk(h[2], h[3]), hpk(h[4], h[5]), hpk(h[6], h[7]));
        }
    }
}

// ======================================================================
// Kernel 3: fused attention, 2 row-blocks per CTA. grid (32, 16), 2 CTA/SM.
// ======================================================================
#define AT_Q 0
#define AT_KP 8192
#define AT_VP 40960
#define AT_ORED 73728
#define AT_MAX 90624
#define AT_SUM 91136
#define AT_SMEM 91648

__global__ __launch_bounds__(256, 2) void attn_fused(const float* __restrict__ Q,
                                                     float* __restrict__ attnp,
                                                     float* __restrict__ outp) {
    uint32_t smb = smem_u32(dsm);
    const int tid = threadIdx.x, lane = tid & 31, w = tid >> 5;
    const int b = blockIdx.y;

    const int wm = w >> 1, wnh = w & 1;
    const int b3 = (lane >> 3) & 1, b4 = lane >> 4, r7 = (lane & 7) * 16;
    const uint32_t qa = smb + AT_Q;
    const uint32_t kp = smb + AT_KP, vp = smb + AT_VP;
    const int rl = wm * 16 + (lane >> 2);
    float* smax = (float*)(dsm + AT_MAX);
    float* ssum = (float*)(dsm + AT_SUM);
    float* Ored = (float*)(dsm + AT_ORED);
    __half* qsm = (__half*)(dsm + AT_Q);

    // ---- stage Kp/Vp fp16 atoms once (cp.async) ----
    {
        const uint4* kh = (const uint4*)(g_KpH + (size_t)b * 16384);
        const uint4* vh = (const uint4*)(g_VpH + (size_t)b * 16384);
#pragma unroll
        for (int i = 0; i < 8; ++i) {
            uint32_t s = (uint32_t)(tid + 256 * i);
            cpa16(smb + AT_KP + s * 16, kh + s);
            cpa16(smb + AT_VP + s * 16, vh + s);
        }
        CP_COMMIT;
    }

    auto build_q = [&](int s0) {
        const float* Qb = Q + ((size_t)b * SS + s0) * DD;
#pragma unroll
        for (int i = 0; i < 4; ++i) {
            int slot = tid + 256 * i;
            int r = slot >> 4, d4 = slot & 15;
            float4 v = *(const float4*)&Qb[(size_t)r * DD + d4 * 4];
            int off = ((r >> 3) * 8 + (d4 >> 1)) * 64 + (r & 7) * 8 + (d4 & 1) * 4;
            *(uint2*)&qsm[off] =
                make_uint2(hpk2(v.x * SCALE, v.y * SCALE), hpk2(v.z * SCALE, v.w * SCALE));
        }
    };

    build_q(blockIdx.x * 128); // block-0 Q while Kp/Vp fly
    CP_WAIT0;
    __syncthreads();

    for (int blk = 0; blk < 2; ++blk) {
        const int s0 = blockIdx.x * 128 + blk * 64;
        if (blk > 0) {
            __syncthreads();
            build_q(s0);
            __syncthreads();
        }

        // ---- scores: Q @ Kp ----
        float c[16][4];
#pragma unroll
        for (int i = 0; i < 16; ++i)
#pragma unroll
            for (int e = 0; e < 4; ++e) c[i][e] = 0.f;

#pragma unroll
        for (int kk = 0; kk < 4; ++kk) {
            uint32_t aq[4];
            uint32_t oA = (uint32_t)(((wm * 2 + b3) * 8 + kk * 2 + b4) * 128 + r7);
            ldm_x4(aq, qa + oA);
#pragma unroll
            for (int nt2 = 0; nt2 < 8; ++nt2) {
                uint32_t bf[4];
                uint32_t oB = (uint32_t)(((wnh * 16 + nt2 * 2 + b4) * 8 + kk * 2 + b3) * 128 + r7);
                ldm_x4(bf, kp + oB);
                mma_fp16(c[nt2 * 2], aq, &bf[0]);
                mma_fp16(c[nt2 * 2 + 1], aq, &bf[2]);
            }
        }

        // ---- softmax over 256 ----
        float m0 = -1e30f, m1 = -1e30f;
#pragma unroll
        for (int nt = 0; nt < 16; ++nt) {
            m0 = fmaxf(m0, fmaxf(c[nt][0], c[nt][1]));
            m1 = fmaxf(m1, fmaxf(c[nt][2], c[nt][3]));
        }
#pragma unroll
        for (int off = 1; off <= 2; off <<= 1) {
            m0 = fmaxf(m0, __shfl_xor_sync(0xffffffffu, m0, off));
            m1 = fmaxf(m1, __shfl_xor_sync(0xffffffffu, m1, off));
        }
        if ((lane & 3) == 0) {
            smax[wnh * 64 + rl] = m0;
            smax[wnh * 64 + rl + 8] = m1;
        }
        __syncthreads();
        m0 = fmaxf(m0, smax[(wnh ^ 1) * 64 + rl]);
        m1 = fmaxf(m1, smax[(wnh ^ 1) * 64 + rl + 8]);

        float s0a = 0.f, s1a = 0.f;
#pragma unroll
        for (int nt = 0; nt < 16; ++nt) {
            c[nt][0] = __expf(c[nt][0] - m0);
            c[nt][1] = __expf(c[nt][1] - m0);
            c[nt][2] = __expf(c[nt][2] - m1);
            c[nt][3] = __expf(c[nt][3] - m1);
            s0a += c[nt][0] + c[nt][1];
            s1a += c[nt][2] + c[nt][3];
        }
#pragma unroll
        for (int off = 1; off <= 2; off <<= 1) {
            s0a += __shfl_xor_sync(0xffffffffu, s0a, off);
            s1a += __shfl_xor_sync(0xffffffffu, s1a, off);
        }
        if ((lane & 3) == 0) {
            ssum[wnh * 64 + rl] = s0a;
            ssum[wnh * 64 + rl + 8] = s1a;
        }
        __syncthreads();
        float inv0 = 1.f / (s0a + ssum[(wnh ^ 1) * 64 + rl]);
        float inv1 = 1.f / (s1a + ssum[(wnh ^ 1) * 64 + rl + 8]);

        // ---- scale probs + attn write ----
        float* abase = attnp + ((size_t)b * SS + s0 + rl) * KPP + wnh * 128 + (lane & 3) * 2;
#pragma unroll
        for (int nt = 0; nt < 16; ++nt) {
            c[nt][0] *= inv0;
            c[nt][1] *= inv0;
            c[nt][2] *= inv1;
            c[nt][3] *= inv1;
            *(float2*)&abase[nt * 8] = make_float2(c[nt][0], c[nt][1]);
            *(float2*)&abase[8 * KPP + nt * 8] = make_float2(c[nt][2], c[nt][3]);
        }

        // ---- out GEMM: P @ Vp, k-half per warp ----
        float oc[8][4];
#pragma unroll
        for (int i = 0; i < 8; ++i)
#pragma unroll
            for (int e = 0; e < 4; ++e) oc[i][e] = 0.f;

#pragma unroll
        for (int t2 = 0; t2 < 8; ++t2) {
            uint32_t pa[4];
            pa[0] = hpk2(c[2 * t2][0], c[2 * t2][1]);
            pa[1] = hpk2(c[2 * t2][2], c[2 * t2][3]);
            pa[2] = hpk2(c[2 * t2 + 1][0], c[2 * t2 + 1][1]);
            pa[3] = hpk2(c[2 * t2 + 1][2], c[2 * t2 + 1][3]);
#pragma unroll
            for (int nt2 = 0; nt2 < 4; ++nt2) {
                uint32_t vf[4];
                uint32_t oV =
                    (uint32_t)(((nt2 * 2 + b4) * 32 + wnh * 16 + t2 * 2 + b3) * 128 + r7);
                ldm_x4(vf, vp + oV);
                mma_fp16(oc[nt2 * 2], pa, &vf[0]);
                mma_fp16(oc[nt2 * 2 + 1], pa, &vf[2]);
            }
        }

        // ---- cross-half reduction + out write ----
        if (wnh == 1) {
#pragma unroll
            for (int nt = 0; nt < 8; ++nt) {
                int col = nt * 8 + (lane & 3) * 2;
                *(float2*)&Ored[rl * 66 + col] = make_float2(oc[nt][0], oc[nt][1]);
                *(float2*)&Ored[(rl + 8) * 66 + col] = make_float2(oc[nt][2], oc[nt][3]);
            }
        }
        __syncthreads();
        if (wnh == 0) {
            float* o0 = outp + ((size_t)b * SS + s0 + rl) * DD;
#pragma unroll
            for (int nt = 0; nt < 8; ++nt) {
                int col = nt * 8 + (lane & 3) * 2;
                float2 r0v = *(float2*)&Ored[rl * 66 + col];
                float2 r1v = *(float2*)&Ored[(rl + 8) * 66 + col];
                *(float2*)&o0[col] = make_float2(oc[nt][0] + r0v.x, oc[nt][1] + r0v.y);
                *(float2*)&o0[8 * DD + col] =
                    make_float2(oc[nt][2] + r1v.x, oc[nt][3] + r1v.y);
            }
        }
    }
}

// ======================================================================
extern "C" void kernel_launch(void* const* d_in, const int* in_sizes, int n_in,
                              void* d_out, int out_size) {
    const float* Q  = (const float*)d_in[0];
    const float* K  = (const float*)d_in[1];
    const float* V  = (const float*)d_in[2];
    const float* Ew = (const float*)d_in[3];
    const float* Eb = (const float*)d_in[4];
    const float* Fw = (const float*)d_in[5];
    const float* Fb = (const float*)d_in[6];

    float* outp  = (float*)d_out;
    float* attnp = outp + (size_t)BB * SS * DD;

    cudaFuncSetAttribute(proj_mma, cudaFuncAttributeMaxDynamicSharedMemorySize, 40960);
    cudaFuncSetAttribute(attn_fused, cudaFuncAttributeMaxDynamicSharedMemorySize, AT_SMEM);

    prepack_W<<<dim3(16, 8, 2), 256>>>(Ew, Fw);
    proj_mma<<<dim3(8, 2, BB), 256, 40960>>>(K, V);
    proj_reduce_atoms<<<dim3(16, 2, BB), 256>>>(Eb, Fb);
    attn_fused<<<dim3(SS / 128, BB), 256, AT_SMEM>>>(Q, attnp, outp);
}

// round 13
// speedup vs baseline: 1.1459x; 1.0410x over previous
#include <cuda_runtime.h>
#include <cuda_fp16.h>
#include <cstdint>

#define BB 16
#define SS 4096
#define DD 64
#define KPP 256
#define QSCALE 0.1803368801f /* 0.125 * log2(e) */

// ---------------- device scratch ----------------
__device__ __half g_part8h[8 * 2 * 16 * 256 * 64]; // fp16 partials, 8MB
__device__ __half g_WH[2 * 8 * 16 * 8192];         // W A-atoms
__device__ __half g_KpH[BB * 256 * 64];            // Kp B-atoms (n=kp, k=d)
__device__ __half g_VpH[BB * 256 * 64];            // Vp B-atoms (n=d, k=kp)

// ---------------- helpers ----------------
__device__ __forceinline__ uint32_t smem_u32(const void* p) {
    uint32_t a;
    asm("{ .reg .u64 t; cvta.to.shared.u64 t, %1; cvt.u32.u64 %0, t; }" : "=r"(a) : "l"(p));
    return a;
}
__device__ __forceinline__ void ldm_x4(uint32_t* r, uint32_t addr) {
    asm volatile("ldmatrix.sync.aligned.m8n8.x4.shared.b16 {%0,%1,%2,%3}, [%4];"
                 : "=r"(r[0]), "=r"(r[1]), "=r"(r[2]), "=r"(r[3]) : "r"(addr));
}
__device__ __forceinline__ void mma_fp16(float* c, const uint32_t* a, const uint32_t* b) {
    asm volatile(
        "mma.sync.aligned.m16n8k16.row.col.f32.f16.f16.f32 "
        "{%0,%1,%2,%3}, {%4,%5,%6,%7}, {%8,%9}, {%0,%1,%2,%3};"
        : "+f"(c[0]), "+f"(c[1]), "+f"(c[2]), "+f"(c[3])
        : "r"(a[0]), "r"(a[1]), "r"(a[2]), "r"(a[3]), "r"(b[0]), "r"(b[1]));
}
__device__ __forceinline__ uint32_t hpk2(float a, float b) {
    __half2 t = __floats2half2_rn(a, b);
    return *reinterpret_cast<uint32_t*>(&t);
}
__device__ __forceinline__ void cpa16(uint32_t dst, const void* src) {
    asm volatile("cp.async.cg.shared.global [%0], [%1], 16;" :: "r"(dst), "l"(src));
}
#define CP_COMMIT asm volatile("cp.async.commit_group;" ::: "memory")
#define CP_WAIT1 asm volatile("cp.async.wait_group 1;" ::: "memory")
#define CP_WAIT0 asm volatile("cp.async.wait_group 0;" ::: "memory")

// ======================================================================
// Kernel 0: prepack W -> fp16 A-atoms. grid (16 st, 8 chunk, 2 proj), 256 thr.
// ======================================================================
__global__ __launch_bounds__(256) void prepack_W(const float* __restrict__ Ew,
                                                 const float* __restrict__ Fw) {
    const int st = blockIdx.x, chunk = blockIdx.y, proj = blockIdx.z;
    const int m = threadIdx.x;
    const float* src = (proj ? Fw : Ew) + (size_t)m * SS + chunk * 512 + st * 32;
    const size_t bb = (size_t)((proj * 8 + chunk) * 16 + st) * 8192;

    float4 f[8];
#pragma unroll
    for (int j = 0; j < 8; ++j) f[j] = *(const float4*)(src + j * 4);
#pragma unroll
    for (int kg = 0; kg < 4; ++kg) {
        float4 a = f[2 * kg], b = f[2 * kg + 1];
        size_t off = bb + (size_t)(((m >> 3) * 4 + kg) * 64 + (m & 7) * 8);
        *(uint4*)&g_WH[off] =
            make_uint4(hpk2(a.x, a.y), hpk2(a.z, a.w), hpk2(b.x, b.y), hpk2(b.z, b.w));
    }
}

extern __shared__ __align__(1024) char dsm[];

// ======================================================================
// Kernel 1: projections (validated R10/R11). W cp.async, X fused LDG->STS.
// ======================================================================
__global__ __launch_bounds__(256, 2) void proj_mma(const float* __restrict__ Kin,
                                                   const float* __restrict__ Vin) {
    uint32_t smb = smem_u32(dsm);
    const int tid = threadIdx.x, lane = tid & 31, w = tid >> 5;
    const int chunk = blockIdx.x, proj = blockIdx.y, b = blockIdx.z;
    const int wm = w & 3, wn = w >> 2;
    const int b3 = (lane >> 3) & 1, b4 = lane >> 4, r7 = (lane & 7) * 16;

    const uint4* wp0 = (const uint4*)(g_WH + (size_t)((proj * 8 + chunk) * 16) * 8192);
    const float* X = (proj ? Vin : Kin) + ((size_t)b * SS + chunk * 512) * DD;

    const int xd = tid & 63, xsg = tid >> 6;
    const uint32_t xsts = (uint32_t)((((xd >> 3) * 4 + xsg) * 64 + (xd & 7) * 8) * 2);

    auto issueW = [&](int st) {
        uint32_t base = smb + (uint32_t)(st & 1) * 20480u;
        const uint4* wp = wp0 + (size_t)st * 1024;
#pragma unroll
        for (int i = 0; i < 4; ++i)
            cpa16(base + (uint32_t)(tid + 256 * i) * 16u, wp + tid + 256 * i);
    };
    auto ldgX = [&](int st, float* v) {
        const float* col = X + (size_t)(st * 32 + xsg * 8) * DD + xd;
#pragma unroll
        for (int e = 0; e < 8; ++e) v[e] = col[e * DD];
    };
    auto stsX = [&](int st, const float* v) {
        uint32_t dst = smb + (uint32_t)(st & 1) * 20480u + 16384u + xsts;
        asm volatile("st.shared.v4.b32 [%0], {%1,%2,%3,%4};"
                     :: "r"(dst), "r"(hpk2(v[0], v[1])), "r"(hpk2(v[2], v[3])),
                        "r"(hpk2(v[4], v[5])), "r"(hpk2(v[6], v[7])));
    };

    float acc[4][4][4];
#pragma unroll
    for (int i = 0; i < 4; ++i)
#pragma unroll
        for (int j = 0; j < 4; ++j)
#pragma unroll
            for (int e = 0; e < 4; ++e) acc[i][j][e] = 0.f;

    float xv[8];
    ldgX(0, xv);
    issueW(0);
    CP_COMMIT;
    stsX(0, xv);

    for (int st = 0; st < 16; ++st) {
        if (st < 15) {
            issueW(st + 1);
            CP_COMMIT;
            ldgX(st + 1, xv);
            CP_WAIT1;
        } else {
            CP_WAIT0;
        }
        __syncthreads();

        const uint32_t bufb = smb + (uint32_t)(st & 1) * 20480u;
        const uint32_t aH = bufb, bH = bufb + 16384u;

#pragma unroll
        for (int kk2 = 0; kk2 < 2; ++kk2) {
            uint32_t af[4][4], bv[2][4];
#pragma unroll
            for (int mt = 0; mt < 4; ++mt) {
                uint32_t o = (uint32_t)(((wm * 8 + mt * 2 + b3) * 4 + kk2 * 2 + b4) * 128 + r7);
                ldm_x4(af[mt], aH + o);
            }
#pragma unroll
            for (int nt2 = 0; nt2 < 2; ++nt2) {
                uint32_t o = (uint32_t)(((wn * 4 + nt2 * 2 + b4) * 4 + kk2 * 2 + b3) * 128 + r7);
                ldm_x4(bv[nt2], bH + o);
            }
#pragma unroll
            for (int mt = 0; mt < 4; ++mt)
#pragma unroll
                for (int nt2 = 0; nt2 < 2; ++nt2)
#pragma unroll
                    for (int hf = 0; hf < 2; ++hf)
                        mma_fp16(acc[mt][nt2 * 2 + hf], af[mt], &bv[nt2][hf * 2]);
        }
        if (st < 15) stsX(st + 1, xv);
        __syncthreads();
    }

    __half* dst = g_part8h + ((size_t)(chunk * 2 + proj) * 16 + b) * 16384;
    const int row = lane >> 2, q2 = (lane & 3) * 2;
#pragma unroll
    for (int mt = 0; mt < 4; ++mt)
#pragma unroll
        for (int nt = 0; nt < 4; ++nt) {
            int m = wm * 64 + mt * 16 + row;
            int n = wn * 32 + nt * 8 + q2;
            *(uint32_t*)&dst[(size_t)m * 64 + n] = hpk2(acc[mt][nt][0], acc[mt][nt][1]);
            *(uint32_t*)&dst[(size_t)(m + 8) * 64 + n] = hpk2(acc[mt][nt][2], acc[mt][nt][3]);
        }
}

// ======================================================================
// Kernel 2: reduce v4. grid (8 kpblk, 2 proj, 16 b), 256 thr.
// ======================================================================
__global__ __launch_bounds__(256) void proj_reduce_atoms(const float* __restrict__ Eb,
                                                         const float* __restrict__ Fb) {
    __shared__ float tile[32][68];
    const int tid = threadIdx.x;
    const int kpblk = blockIdx.x, p = blockIdx.y, b = blockIdx.z;

    const int r = tid >> 3, dseg = tid & 7;
    float acc[8];
#pragma unroll
    for (int j = 0; j < 8; ++j) acc[j] = 0.f;

    const size_t eoff = (size_t)(kpblk * 32 + r) * 64 + dseg * 8;
#pragma unroll
    for (int c = 0; c < 8; ++c) {
        uint4 u = *(const uint4*)&g_part8h[((size_t)(c * 2 + p) * 16 + b) * 16384 + eoff];
        float2 v0 = __half22float2(*reinterpret_cast<__half2*>(&u.x));
        float2 v1 = __half22float2(*reinterpret_cast<__half2*>(&u.y));
        float2 v2 = __half22float2(*reinterpret_cast<__half2*>(&u.z));
        float2 v3 = __half22float2(*reinterpret_cast<__half2*>(&u.w));
        acc[0] += v0.x; acc[1] += v0.y; acc[2] += v1.x; acc[3] += v1.y;
        acc[4] += v2.x; acc[5] += v2.y; acc[6] += v3.x; acc[7] += v3.y;
    }
    const float bv = (p ? Fb : Eb)[kpblk * 32 + r];
#pragma unroll
    for (int j = 0; j < 8; ++j) acc[j] += bv;

    if (p == 0) {
        size_t gbase = (size_t)b * 16384 +
                       (size_t)(((kpblk * 4 + (r >> 3)) * 8 + dseg)) * 64 + (r & 7) * 8;
        *(uint4*)&g_KpH[gbase] = make_uint4(hpk2(acc[0], acc[1]), hpk2(acc[2], acc[3]),
                                            hpk2(acc[4], acc[5]), hpk2(acc[6], acc[7]));
    } else {
        *(float4*)&tile[r][dseg * 8] = make_float4(acc[0], acc[1], acc[2], acc[3]);
        *(float4*)&tile[r][dseg * 8 + 4] = make_float4(acc[4], acc[5], acc[6], acc[7]);
        __syncthreads();
        const int a = tid >> 3, rr = tid & 7;
        const int gd = a >> 2, gk = a & 3;
        float v[8];
#pragma unroll
        for (int j = 0; j < 8; ++j) v[j] = tile[gk * 8 + j][gd * 8 + rr];
        size_t gbase =
            (size_t)b * 16384 + (size_t)((gd * 32 + kpblk * 4 + gk)) * 64 + rr * 8;
        *(uint4*)&g_VpH[gbase] = make_uint4(hpk2(v[0], v[1]), hpk2(v[2], v[3]),
                                            hpk2(v[4], v[5]), hpk2(v[6], v[7]));
    }
}

// ======================================================================
// Kernel 3: fused attention with smem-staged coalesced output flush.
// grid (32, 16), 256 thr, 106KB smem, 2 CTA/SM.
// Ored row stride = 68 floats (272 B, 16B-aligned).
// ======================================================================
#define AT_Q 0
#define AT_KP 8192
#define AT_VP 40960
#define AT_PS 73728 /* __half[64][264] = 33792 B; reused as float Ored[64][68] = 17408 B */
#define AT_MAX 107520
#define AT_SUM 108032
#define AT_SMEM 108544

__global__ __launch_bounds__(256, 2) void attn_fused(const float* __restrict__ Q,
                                                     float* __restrict__ attnp,
                                                     float* __restrict__ outp) {
    uint32_t smb = smem_u32(dsm);
    const int tid = threadIdx.x, lane = tid & 31, w = tid >> 5;
    const int b = blockIdx.y;

    const int wm = w >> 1, wnh = w & 1;
    const int b3 = (lane >> 3) & 1, b4 = lane >> 4, r7 = (lane & 7) * 16;
    const uint32_t qa = smb + AT_Q;
    const uint32_t kp = smb + AT_KP, vp = smb + AT_VP;
    const int rl = wm * 16 + (lane >> 2);
    float* smax = (float*)(dsm + AT_MAX);
    float* ssum = (float*)(dsm + AT_SUM);
    __half* qsm = (__half*)(dsm + AT_Q);

    // ---- stage Kp/Vp fp16 atoms once (cp.async) ----
    {
        const uint4* kh = (const uint4*)(g_KpH + (size_t)b * 16384);
        const uint4* vh = (const uint4*)(g_VpH + (size_t)b * 16384);
#pragma unroll
        for (int i = 0; i < 8; ++i) {
            uint32_t s = (uint32_t)(tid + 256 * i);
            cpa16(smb + AT_KP + s * 16, kh + s);
            cpa16(smb + AT_VP + s * 16, vh + s);
        }
        CP_COMMIT;
    }

    auto build_q = [&](int s0) {
        const float* Qb = Q + ((size_t)b * SS + s0) * DD;
#pragma unroll
        for (int i = 0; i < 4; ++i) {
            int slot = tid + 256 * i;
            int r = slot >> 4, d4 = slot & 15;
            float4 v = *(const float4*)&Qb[(size_t)r * DD + d4 * 4];
            int off = ((r >> 3) * 8 + (d4 >> 1)) * 64 + (r & 7) * 8 + (d4 & 1) * 4;
            *(uint2*)&qsm[off] =
                make_uint2(hpk2(v.x * QSCALE, v.y * QSCALE), hpk2(v.z * QSCALE, v.w * QSCALE));
        }
    };

    build_q(blockIdx.x * 128);
    CP_WAIT0;
    __syncthreads();

    for (int blk = 0; blk < 2; ++blk) {
        const int s0 = blockIdx.x * 128 + blk * 64;
        if (blk > 0) {
            __syncthreads();
            build_q(s0);
            __syncthreads();
        }

        // ---- scores: Q @ Kp (log2 domain) ----
        float c[16][4];
#pragma unroll
        for (int i = 0; i < 16; ++i)
#pragma unroll
            for (int e = 0; e < 4; ++e) c[i][e] = 0.f;

#pragma unroll
        for (int kk = 0; kk < 4; ++kk) {
            uint32_t aq[4];
            uint32_t oA = (uint32_t)(((wm * 2 + b3) * 8 + kk * 2 + b4) * 128 + r7);
            ldm_x4(aq, qa + oA);
#pragma unroll
            for (int nt2 = 0; nt2 < 8; ++nt2) {
                uint32_t bf[4];
                uint32_t oB = (uint32_t)(((wnh * 16 + nt2 * 2 + b4) * 8 + kk * 2 + b3) * 128 + r7);
                ldm_x4(bf, kp + oB);
                mma_fp16(c[nt2 * 2], aq, &bf[0]);
                mma_fp16(c[nt2 * 2 + 1], aq, &bf[2]);
            }
        }

        // ---- softmax over 256 (exp2) ----
        float m0 = -1e30f, m1 = -1e30f;
#pragma unroll
        for (int nt = 0; nt < 16; ++nt) {
            m0 = fmaxf(m0, fmaxf(c[nt][0], c[nt][1]));
            m1 = fmaxf(m1, fmaxf(c[nt][2], c[nt][3]));
        }
#pragma unroll
        for (int off = 1; off <= 2; off <<= 1) {
            m0 = fmaxf(m0, __shfl_xor_sync(0xffffffffu, m0, off));
            m1 = fmaxf(m1, __shfl_xor_sync(0xffffffffu, m1, off));
        }
        if ((lane & 3) == 0) {
            smax[wnh * 64 + rl] = m0;
            smax[wnh * 64 + rl + 8] = m1;
        }
        __syncthreads();
        m0 = fmaxf(m0, smax[(wnh ^ 1) * 64 + rl]);
        m1 = fmaxf(m1, smax[(wnh ^ 1) * 64 + rl + 8]);

        float s0a = 0.f, s1a = 0.f;
#pragma unroll
        for (int nt = 0; nt < 16; ++nt) {
            c[nt][0] = exp2f(c[nt][0] - m0);
            c[nt][1] = exp2f(c[nt][1] - m0);
            c[nt][2] = exp2f(c[nt][2] - m1);
            c[nt][3] = exp2f(c[nt][3] - m1);
            s0a += c[nt][0] + c[nt][1];
            s1a += c[nt][2] + c[nt][3];
        }
#pragma unroll
        for (int off = 1; off <= 2; off <<= 1) {
            s0a += __shfl_xor_sync(0xffffffffu, s0a, off);
            s1a += __shfl_xor_sync(0xffffffffu, s1a, off);
        }
        if ((lane & 3) == 0) {
            ssum[wnh * 64 + rl] = s0a;
            ssum[wnh * 64 + rl + 8] = s1a;
        }
        __syncthreads();
        float inv0 = 1.f / (s0a + ssum[(wnh ^ 1) * 64 + rl]);
        float inv1 = 1.f / (s1a + ssum[(wnh ^ 1) * 64 + rl + 8]);

        // ---- scale + stage P into smem (fp16) ----
        {
            uint32_t pbase0 = smb + AT_PS + (uint32_t)rl * 528u +
                              (uint32_t)(wnh * 128 + (lane & 3) * 2) * 2u;
#pragma unroll
            for (int nt = 0; nt < 16; ++nt) {
                c[nt][0] *= inv0;
                c[nt][1] *= inv0;
                c[nt][2] *= inv1;
                c[nt][3] *= inv1;
                uint32_t a01 = hpk2(c[nt][0], c[nt][1]);
                uint32_t a23 = hpk2(c[nt][2], c[nt][3]);
                asm volatile("st.shared.b32 [%0], %1;" :: "r"(pbase0 + nt * 16u), "r"(a01));
                asm volatile("st.shared.b32 [%0], %1;"
                             :: "r"(pbase0 + 8u * 528u + nt * 16u), "r"(a23));
            }
        }

        // ---- out GEMM: P(regs) @ Vp, k-half per warp ----
        float oc[8][4];
#pragma unroll
        for (int i = 0; i < 8; ++i)
#pragma unroll
            for (int e = 0; e < 4; ++e) oc[i][e] = 0.f;

#pragma unroll
        for (int t2 = 0; t2 < 8; ++t2) {
            uint32_t pa[4];
            pa[0] = hpk2(c[2 * t2][0], c[2 * t2][1]);
            pa[1] = hpk2(c[2 * t2][2], c[2 * t2][3]);
            pa[2] = hpk2(c[2 * t2 + 1][0], c[2 * t2 + 1][1]);
            pa[3] = hpk2(c[2 * t2 + 1][2], c[2 * t2 + 1][3]);
#pragma unroll
            for (int nt2 = 0; nt2 < 4; ++nt2) {
                uint32_t vf[4];
                uint32_t oV =
                    (uint32_t)(((nt2 * 2 + b4) * 32 + wnh * 16 + t2 * 2 + b3) * 128 + r7);
                ldm_x4(vf, vp + oV);
                mma_fp16(oc[nt2 * 2], pa, &vf[0]);
                mma_fp16(oc[nt2 * 2 + 1], pa, &vf[2]);
            }
        }

        __syncthreads(); // P fully staged

        // ---- coalesced P flush: 16 x (LDS.64 -> float4 STG) ----
        {
            const __half* ps = (const __half*)(dsm + AT_PS);
            float* ab = attnp + ((size_t)b * SS + s0) * KPP;
#pragma unroll
            for (int it = 0; it < 16; ++it) {
                int idx = tid + 256 * it;
                int row = idx >> 6, seg = idx & 63;
                uint2 u = *(const uint2*)(ps + row * 264 + seg * 4);
                float2 f0 = __half22float2(*reinterpret_cast<__half2*>(&u.x));
                float2 f1 = __half22float2(*reinterpret_cast<__half2*>(&u.y));
                *(float4*)&ab[(size_t)row * KPP + seg * 4] = make_float4(f0.x, f0.y, f1.x, f1.y);
            }
        }
        __syncthreads(); // Ps region free

        // ---- out k-reduction via Ored (in Ps region), stride 68 ----
        float* Ored = (float*)(dsm + AT_PS); // [64][68]
        if (wnh == 1) {
#pragma unroll
            for (int nt = 0; nt < 8; ++nt) {
                int col = nt * 8 + (lane & 3) * 2;
                *(float2*)&Ored[rl * 68 + col] = make_float2(oc[nt][0], oc[nt][1]);
                *(float2*)&Ored[(rl + 8) * 68 + col] = make_float2(oc[nt][2], oc[nt][3]);
            }
        }
        __syncthreads();
        if (wnh == 0) {
#pragma unroll
            for (int nt = 0; nt < 8; ++nt) {
                int col = nt * 8 + (lane & 3) * 2;
                float2 r0v = *(float2*)&Ored[rl * 68 + col];
                float2 r1v = *(float2*)&Ored[(rl + 8) * 68 + col];
                *(float2*)&Ored[rl * 68 + col] =
                    make_float2(oc[nt][0] + r0v.x, oc[nt][1] + r0v.y);
                *(float2*)&Ored[(rl + 8) * 68 + col] =
                    make_float2(oc[nt][2] + r1v.x, oc[nt][3] + r1v.y);
            }
        }
        __syncthreads();

        // ---- coalesced out flush: 4 x (LDS.128 -> float4 STG) ----
        {
            float* ob = outp + ((size_t)b * SS + s0) * DD;
#pragma unroll
            for (int it = 0; it < 4; ++it) {
                int idx = tid + 256 * it;
                int row = idx >> 4, seg = idx & 15;
                float4 v = *(const float4*)&Ored[row * 68 + seg * 4];
                *(float4*)&ob[(size_t)row * DD + seg * 4] = v;
            }
        }
    }
}

// ======================================================================
extern "C" void kernel_launch(void* const* d_in, const int* in_sizes, int n_in,
                              void* d_out, int out_size) {
    const float* Q  = (const float*)d_in[0];
    const float* K  = (const float*)d_in[1];
    const float* V  = (const float*)d_in[2];
    const float* Ew = (const float*)d_in[3];
    const float* Eb = (const float*)d_in[4];
    const float* Fw = (const float*)d_in[5];
    const float* Fb = (const float*)d_in[6];

    float* outp  = (float*)d_out;
    float* attnp = outp + (size_t)BB * SS * DD;

    cudaFuncSetAttribute(proj_mma, cudaFuncAttributeMaxDynamicSharedMemorySize, 40960);
    cudaFuncSetAttribute(attn_fused, cudaFuncAttributeMaxDynamicSharedMemorySize, AT_SMEM);

    prepack_W<<<dim3(16, 8, 2), 256>>>(Ew, Fw);
    proj_mma<<<dim3(8, 2, BB), 256, 40960>>>(K, V);
    proj_reduce_atoms<<<dim3(8, 2, BB), 256>>>(Eb, Fb);
    attn_fused<<<dim3(SS / 128, BB), 256, AT_SMEM>>>(Q, attnp, outp);
}